// round 10
// baseline (speedup 1.0000x reference)
#include <cuda_runtime.h>
#include <cuda_fp16.h>
#include <cstdint>

#define T_TOK 8192
#define DIM   1024
#define FF    4096
#define NE    8

// ---------------- device scratch (static: no allocations allowed) ----------
// NOTE: these symbols must ONLY be referenced from device code. Passing them
// as kernel arguments from host code yields the host-side shadow address,
// which on GB300 (ATS) silently resolves to HOST memory (~200 GB/s) — the
// root cause of the R6/R8 6.1 ms regression.
__device__ int    g_expert[T_TOK];
__device__ float  g_gate[T_TOK];
__device__ int    g_counts[NE];
__device__ int    g_cursor[NE];
__device__ int    g_offs[NE];
__device__ float  g_gatesum[NE];
__device__ int    g_perm[T_TOK];
__device__ __half g_hh[(size_t)T_TOK * FF];   // 67 MB fp16 H scratch
__device__ __align__(128) __half g_w1h[(size_t)NE * DIM * FF];  // fp16 W1 [E][D][F]
__device__ __align__(128) __half g_w2h[(size_t)NE * FF * DIM];  // fp16 W2 [E][F][D]

// ---------------- helpers ---------------------------------------------------
__device__ __forceinline__ void mma16(float* c, const uint32_t* a, const uint32_t* b) {
    asm volatile(
        "mma.sync.aligned.m16n8k16.row.col.f32.f16.f16.f32 "
        "{%0,%1,%2,%3}, {%4,%5,%6,%7}, {%8,%9}, {%0,%1,%2,%3};"
        : "+f"(c[0]), "+f"(c[1]), "+f"(c[2]), "+f"(c[3])
        : "r"(a[0]), "r"(a[1]), "r"(a[2]), "r"(a[3]), "r"(b[0]), "r"(b[1]));
}

__device__ __forceinline__ void ldmat4(uint32_t* r, const __half* p) {
    uint32_t sa = (uint32_t)__cvta_generic_to_shared(p);
    asm volatile("ldmatrix.sync.aligned.m8n8.x4.shared.b16 {%0,%1,%2,%3}, [%4];"
        : "=r"(r[0]), "=r"(r[1]), "=r"(r[2]), "=r"(r[3]) : "r"(sa));
}

__device__ __forceinline__ void ldmat4t(uint32_t* r, const __half* p) {
    uint32_t sa = (uint32_t)__cvta_generic_to_shared(p);
    asm volatile("ldmatrix.sync.aligned.m8n8.x4.trans.shared.b16 {%0,%1,%2,%3}, [%4];"
        : "=r"(r[0]), "=r"(r[1]), "=r"(r[2]), "=r"(r[3]) : "r"(sa));
}

__device__ __forceinline__ uint32_t pack_h2(float x, float y) {
    __half2 h = __floats2half2_rn(x, y);
    return *reinterpret_cast<uint32_t*>(&h);
}

// ---------------- 1. init --------------------------------------------------
__global__ void init_kernel() {
    int i = threadIdx.x;
    if (i < NE) { g_counts[i] = 0; g_gatesum[i] = 0.f; }
}

// ---------------- 2. router (one warp per token) ----------------------------
__global__ void router_kernel(const float* __restrict__ x,
                              const float* __restrict__ rw,
                              const float* __restrict__ rb) {
    __shared__ float s_rw[NE * DIM];
    const int tid = threadIdx.x;
    for (int i = tid; i < NE * DIM / 4; i += blockDim.x)
        ((float4*)s_rw)[i] = ((const float4*)rw)[i];
    __syncthreads();

    const int warp = tid >> 5, lane = tid & 31;
    const int t = blockIdx.x * 8 + warp;

    float acc[NE];
#pragma unroll
    for (int e = 0; e < NE; e++) acc[e] = 0.f;

    const float4* xv = (const float4*)(x + (size_t)t * DIM);
#pragma unroll
    for (int i = 0; i < 8; i++) {
        float4 xx = xv[lane + i * 32];
#pragma unroll
        for (int e = 0; e < NE; e++) {
            float4 ww = ((const float4*)(s_rw + e * DIM))[lane + i * 32];
            acc[e] += xx.x * ww.x + xx.y * ww.y + xx.z * ww.z + xx.w * ww.w;
        }
    }
#pragma unroll
    for (int e = 0; e < NE; e++)
#pragma unroll
        for (int o = 16; o > 0; o >>= 1)
            acc[e] += __shfl_xor_sync(0xffffffffu, acc[e], o);

    if (lane == 0) {
        float mx = -1e30f; int arg = 0;
#pragma unroll
        for (int e = 0; e < NE; e++) {
            acc[e] += rb[e];
            if (acc[e] > mx) { mx = acc[e]; arg = e; }   // first-max, matches argmax
        }
        float s = 0.f;
#pragma unroll
        for (int e = 0; e < NE; e++) s += expf(acc[e] - mx);
        float gate = 1.f / s;                            // max softmax prob
        g_expert[t] = arg;
        g_gate[t]   = gate;
        atomicAdd(&g_counts[arg], 1);
        atomicAdd(&g_gatesum[arg], gate);
    }
}

// ---------------- 3. offsets + aux loss -------------------------------------
__global__ void offs_loss_kernel(float* __restrict__ loss_out) {
    if (threadIdx.x == 0) {
        int off = 0; float loss = 0.f;
        for (int e = 0; e < NE; e++) {
            g_offs[e] = off;
            g_cursor[e] = off;
            float frac = (float)g_counts[e] / (float)T_TOK;
            float prob = g_gatesum[e] / ((float)T_TOK * (float)T_TOK);
            loss += frac * prob;
            off += g_counts[e];
        }
        *loss_out = loss * 3e-06f * (float)NE;
    }
}

// ---------------- 4. scatter token ids into expert-sorted order -------------
__global__ void scatter_kernel() {
    int t = blockIdx.x * blockDim.x + threadIdx.x;
    int e = g_expert[t];
    int pos = atomicAdd(&g_cursor[e], 1);
    g_perm[pos] = t;
}

// ---------------- 4b. weight fp32 -> fp16 (device-symbol dst selected by W) --
template <int W>
__global__ void conv_kernel(const float* __restrict__ in) {
    const size_t n4 = (size_t)NE * DIM * FF / 4;
    size_t i = (size_t)blockIdx.x * blockDim.x + threadIdx.x;
    if (i >= n4) return;
    __half* out = (W == 1) ? g_w1h : g_w2h;   // device-side symbol reference
    float4 v = ((const float4*)in)[i];
    uint2 u;
    u.x = pack_h2(v.x, v.y);
    u.y = pack_h2(v.z, v.w);
    ((uint2*)out)[i] = u;
}

// ---------------- 5/6. grouped GEMM (fp16 mma.sync m16n8k16, 128x128x32) ----
// MODE 1: H[off+p, :] = relu( x[perm[off+p], :] @ W1h[e] )   fp16-stored
// MODE 2: out[t, :]   = ( H[off+p, :] @ W2h[e] ) * gate[t]
template <int MODE, int KDIM, int NDIM>
__global__ void __launch_bounds__(256) moe_gemm(const float* __restrict__ Asrc,
                                                float* __restrict__ Out) {
    constexpr int LDA = 40;    // halves: 80B row pitch -> conflict-free ldmatrix
    constexpr int LDB = 136;   // halves: 272B row pitch -> conflict-free ldmatrix.trans
    __shared__ __align__(16) __half As[128 * LDA];
    __shared__ __align__(16) __half Bs[32 * LDB];

    const int e   = blockIdx.z;
    const int cnt = g_counts[e];
    const int r0  = blockIdx.y * 128;
    if (r0 >= cnt) return;
    const int off = g_offs[e];
    const int n0  = blockIdx.x * 128;

    const int tid  = threadIdx.x;
    const int lane = tid & 31;
    const int gq   = lane >> 2;
    const int tg   = lane & 3;
    const int w    = tid >> 5;
    const int wm   = w & 1;        // 2 warps along M (64 each)
    const int wn   = w >> 1;       // 4 warps along N (32 each)

    // -- A global load mapping: 4 rows/thread, 4 k-elements per row per chunk
    const int arow = tid >> 3;     // 0..31
    const int ak4  = tid & 7;      // 0..7 (4-elem group within BK=32)
    const float*  aptrf[4];
    const __half* aptrh[4];
    bool aval[4];
#pragma unroll
    for (int j = 0; j < 4; j++) {
        int p = r0 + arow + 32 * j;
        bool v = p < cnt;
        aval[j] = v;
        if (MODE == 1) {
            int src = v ? g_perm[off + p] : 0;
            aptrf[j] = Asrc + (size_t)src * KDIM;
        } else {
            int src = v ? (off + p) : 0;
            aptrh[j] = g_hh + (size_t)src * KDIM;
        }
    }

    // -- B global load mapping: 2 k-rows/thread, one uint4 (8 halves) each
    const int br = tid >> 4;       // 0..15 (and +16)
    const int bc = tid & 15;       // 16B chunk within 128-half row
    const __half* whbase = (MODE == 1 ? g_w1h : g_w2h)   // device-side symbol
                           + (size_t)e * DIM * FF + n0;

    float acc[4][4][4];
#pragma unroll
    for (int i = 0; i < 4; i++)
#pragma unroll
        for (int jn = 0; jn < 4; jn++)
#pragma unroll
            for (int r = 0; r < 4; r++) acc[i][jn][r] = 0.f;

    // register staging for 2-stage software pipeline
    float4 rAf[4];
    float2 rAh[4];
    uint4  rBu[2];

    auto load_stage = [&](int kb) {
#pragma unroll
        for (int j = 0; j < 4; j++) {
            if (MODE == 1) {
                rAf[j] = aval[j] ? ((const float4*)(aptrf[j] + kb))[ak4]
                                 : make_float4(0.f, 0.f, 0.f, 0.f);
            } else {
                rAh[j] = aval[j] ? ((const float2*)(aptrh[j] + kb))[ak4]
                                 : make_float2(0.f, 0.f);
            }
        }
        const __half* bg = whbase + (size_t)(kb + br) * NDIM + bc * 8;
        rBu[0] = *(const uint4*)bg;
        rBu[1] = *(const uint4*)(bg + (size_t)16 * NDIM);
    };

    auto store_stage = [&]() {
#pragma unroll
        for (int j = 0; j < 4; j++) {
            __half* dst = As + (arow + 32 * j) * LDA + ak4 * 4;
            uint2 u;
            if (MODE == 1) {
                u.x = pack_h2(rAf[j].x, rAf[j].y);
                u.y = pack_h2(rAf[j].z, rAf[j].w);
            } else {
                u = *reinterpret_cast<uint2*>(&rAh[j]);   // raw 4 halves
            }
            *reinterpret_cast<uint2*>(dst) = u;
        }
        *reinterpret_cast<uint4*>(Bs + br * LDB + bc * 8)        = rBu[0];
        *reinterpret_cast<uint4*>(Bs + (br + 16) * LDB + bc * 8) = rBu[1];
    };

    load_stage(0);

    for (int kb = 0; kb < KDIM; kb += 32) {
        store_stage();
        __syncthreads();
        if (kb + 32 < KDIM) load_stage(kb + 32);   // overlap next LDG with math

#pragma unroll
        for (int kk = 0; kk < 2; kk++) {           // two k16 steps
            uint32_t af[4][4];
#pragma unroll
            for (int mt = 0; mt < 4; mt++) {
                const __half* p = As + (wm * 64 + mt * 16 + (lane & 15)) * LDA
                                     + kk * 16 + (lane >> 4) * 8;
                ldmat4(af[mt], p);
            }
            uint32_t bf[4][2];
#pragma unroll
            for (int nn = 0; nn < 2; nn++) {
                const __half* p = Bs + (kk * 16 + (lane & 15)) * LDB
                                     + wn * 32 + nn * 16 + (lane >> 4) * 8;
                uint32_t r[4];
                ldmat4t(r, p);
                bf[nn * 2 + 0][0] = r[0]; bf[nn * 2 + 0][1] = r[1];
                bf[nn * 2 + 1][0] = r[2]; bf[nn * 2 + 1][1] = r[3];
            }
#pragma unroll
            for (int mt = 0; mt < 4; mt++)
#pragma unroll
                for (int nt = 0; nt < 4; nt++)
                    mma16(acc[mt][nt], af[mt], bf[nt]);
        }
        __syncthreads();
    }

    // -- epilogue (c frag: c0,c1 = row g cols 2tg,2tg+1; c2,c3 = row g+8)
#pragma unroll
    for (int mt = 0; mt < 4; mt++) {
#pragma unroll
        for (int rr = 0; rr < 2; rr++) {
            int p = r0 + wm * 64 + mt * 16 + gq + rr * 8;
            if (p >= cnt) continue;
            if (MODE == 1) {
                __half* hrow = g_hh + (size_t)(off + p) * FF + n0 + wn * 32;
#pragma unroll
                for (int nt = 0; nt < 4; nt++) {
                    uint32_t v = pack_h2(fmaxf(acc[mt][nt][rr * 2 + 0], 0.f),
                                         fmaxf(acc[mt][nt][rr * 2 + 1], 0.f));
                    *reinterpret_cast<uint32_t*>(hrow + nt * 8 + tg * 2) = v;
                }
            } else {
                int t = g_perm[off + p];
                float gate = g_gate[t];
                float* orow = Out + (size_t)t * DIM + n0 + wn * 32;
#pragma unroll
                for (int nt = 0; nt < 4; nt++) {
                    float2 v;
                    v.x = acc[mt][nt][rr * 2 + 0] * gate;
                    v.y = acc[mt][nt][rr * 2 + 1] * gate;
                    *((float2*)(orow + nt * 8 + tg * 2)) = v;
                }
            }
        }
    }
}

// ---------------- launch -----------------------------------------------------
extern "C" void kernel_launch(void* const* d_in, const int* in_sizes, int n_in,
                              void* d_out, int out_size) {
    const float* x  = (const float*)d_in[0];
    const float* w1 = (const float*)d_in[1];
    const float* w2 = (const float*)d_in[2];
    const float* rw = (const float*)d_in[3];
    const float* rb = (const float*)d_in[4];
    float* out = (float*)d_out;

    const size_t wn4 = (size_t)NE * DIM * FF / 4;
    const int convgrid = (int)((wn4 + 255) / 256);

    init_kernel<<<1, 32>>>();
    router_kernel<<<T_TOK / 8, 256>>>(x, rw, rb);
    offs_loss_kernel<<<1, 32>>>(out + (size_t)out_size - 1);  // loss is last element
    scatter_kernel<<<T_TOK / 256, 256>>>();
    conv_kernel<1><<<convgrid, 256>>>(w1);
    conv_kernel<2><<<convgrid, 256>>>(w2);
    moe_gemm<1, DIM, FF><<<dim3(FF / 128, T_TOK / 128, NE), 256>>>(x,  nullptr);
    moe_gemm<2, FF, DIM><<<dim3(DIM / 128, T_TOK / 128, NE), 256>>>(nullptr, out);
}

// round 11
// speedup vs baseline: 1.0011x; 1.0011x over previous
#include <cuda_runtime.h>
#include <cuda_fp16.h>
#include <cstdint>

#define T_TOK 8192
#define DIM   1024
#define FF    4096
#define NE    8

// ---------------- device scratch (static: no allocations allowed) ----------
// NOTE: these symbols must ONLY be referenced from device code. Passing them
// as kernel arguments from host code yields the host-side shadow address,
// which on GB300 (ATS) silently resolves to HOST memory (~200 GB/s) — the
// root cause of the R6/R8 6.1 ms regression.
__device__ int    g_expert[T_TOK];
__device__ float  g_gate[T_TOK];
__device__ int    g_counts[NE];
__device__ int    g_cursor[NE];
__device__ int    g_offs[NE];
__device__ float  g_gatesum[NE];
__device__ int    g_perm[T_TOK];
__device__ __half g_hh[(size_t)T_TOK * FF];   // 67 MB fp16 H scratch
__device__ __align__(128) __half g_w1h[(size_t)NE * DIM * FF];  // fp16 W1 [E][D][F]
__device__ __align__(128) __half g_w2h[(size_t)NE * FF * DIM];  // fp16 W2 [E][F][D]

// ---------------- helpers ---------------------------------------------------
__device__ __forceinline__ void mma16(float* c, const uint32_t* a, const uint32_t* b) {
    asm volatile(
        "mma.sync.aligned.m16n8k16.row.col.f32.f16.f16.f32 "
        "{%0,%1,%2,%3}, {%4,%5,%6,%7}, {%8,%9}, {%0,%1,%2,%3};"
        : "+f"(c[0]), "+f"(c[1]), "+f"(c[2]), "+f"(c[3])
        : "r"(a[0]), "r"(a[1]), "r"(a[2]), "r"(a[3]), "r"(b[0]), "r"(b[1]));
}

__device__ __forceinline__ void ldmat4(uint32_t* r, const __half* p) {
    uint32_t sa = (uint32_t)__cvta_generic_to_shared(p);
    asm volatile("ldmatrix.sync.aligned.m8n8.x4.shared.b16 {%0,%1,%2,%3}, [%4];"
        : "=r"(r[0]), "=r"(r[1]), "=r"(r[2]), "=r"(r[3]) : "r"(sa));
}

__device__ __forceinline__ void ldmat4t(uint32_t* r, const __half* p) {
    uint32_t sa = (uint32_t)__cvta_generic_to_shared(p);
    asm volatile("ldmatrix.sync.aligned.m8n8.x4.trans.shared.b16 {%0,%1,%2,%3}, [%4];"
        : "=r"(r[0]), "=r"(r[1]), "=r"(r[2]), "=r"(r[3]) : "r"(sa));
}

__device__ __forceinline__ uint32_t pack_h2(float x, float y) {
    __half2 h = __floats2half2_rn(x, y);
    return *reinterpret_cast<uint32_t*>(&h);
}

// ---------------- 1. init --------------------------------------------------
__global__ void init_kernel() {
    int i = threadIdx.x;
    if (i < NE) { g_counts[i] = 0; g_gatesum[i] = 0.f; }
}

// ---------------- 2. router (one warp per token) ----------------------------
__global__ void router_kernel(const float* __restrict__ x,
                              const float* __restrict__ rw,
                              const float* __restrict__ rb) {
    __shared__ float s_rw[NE * DIM];
    const int tid = threadIdx.x;
    for (int i = tid; i < NE * DIM / 4; i += blockDim.x)
        ((float4*)s_rw)[i] = ((const float4*)rw)[i];
    __syncthreads();

    const int warp = tid >> 5, lane = tid & 31;
    const int t = blockIdx.x * 8 + warp;

    float acc[NE];
#pragma unroll
    for (int e = 0; e < NE; e++) acc[e] = 0.f;

    const float4* xv = (const float4*)(x + (size_t)t * DIM);
#pragma unroll
    for (int i = 0; i < 8; i++) {
        float4 xx = xv[lane + i * 32];
#pragma unroll
        for (int e = 0; e < NE; e++) {
            float4 ww = ((const float4*)(s_rw + e * DIM))[lane + i * 32];
            acc[e] += xx.x * ww.x + xx.y * ww.y + xx.z * ww.z + xx.w * ww.w;
        }
    }
#pragma unroll
    for (int e = 0; e < NE; e++)
#pragma unroll
        for (int o = 16; o > 0; o >>= 1)
            acc[e] += __shfl_xor_sync(0xffffffffu, acc[e], o);

    if (lane == 0) {
        float mx = -1e30f; int arg = 0;
#pragma unroll
        for (int e = 0; e < NE; e++) {
            acc[e] += rb[e];
            if (acc[e] > mx) { mx = acc[e]; arg = e; }   // first-max, matches argmax
        }
        float s = 0.f;
#pragma unroll
        for (int e = 0; e < NE; e++) s += expf(acc[e] - mx);
        float gate = 1.f / s;                            // max softmax prob
        g_expert[t] = arg;
        g_gate[t]   = gate;
        atomicAdd(&g_counts[arg], 1);
        atomicAdd(&g_gatesum[arg], gate);
    }
}

// ---------------- 3. offsets + aux loss -------------------------------------
__global__ void offs_loss_kernel(float* __restrict__ loss_out) {
    if (threadIdx.x == 0) {
        int off = 0; float loss = 0.f;
        for (int e = 0; e < NE; e++) {
            g_offs[e] = off;
            g_cursor[e] = off;
            float frac = (float)g_counts[e] / (float)T_TOK;
            float prob = g_gatesum[e] / ((float)T_TOK * (float)T_TOK);
            loss += frac * prob;
            off += g_counts[e];
        }
        *loss_out = loss * 3e-06f * (float)NE;
    }
}

// ---------------- 4. scatter token ids into expert-sorted order -------------
__global__ void scatter_kernel() {
    int t = blockIdx.x * blockDim.x + threadIdx.x;
    int e = g_expert[t];
    int pos = atomicAdd(&g_cursor[e], 1);
    g_perm[pos] = t;
}

// ---------------- 4b. weight fp32 -> fp16 (device-symbol dst selected by W) --
template <int W>
__global__ void conv_kernel(const float* __restrict__ in) {
    const size_t n4 = (size_t)NE * DIM * FF / 4;
    size_t i = (size_t)blockIdx.x * blockDim.x + threadIdx.x;
    if (i >= n4) return;
    __half* out = (W == 1) ? g_w1h : g_w2h;   // device-side symbol reference
    float4 v = ((const float4*)in)[i];
    uint2 u;
    u.x = pack_h2(v.x, v.y);
    u.y = pack_h2(v.z, v.w);
    ((uint2*)out)[i] = u;
}

// ---------------- 5/6. grouped GEMM (fp16 mma.sync m16n8k16, 128x128x32) ----
// MODE 1: H[off+p, :] = relu( x[perm[off+p], :] @ W1h[e] )   fp16-stored
// MODE 2: out[t, :]   = ( H[off+p, :] @ W2h[e] ) * gate[t]
template <int MODE, int KDIM, int NDIM>
__global__ void __launch_bounds__(256) moe_gemm(const float* __restrict__ Asrc,
                                                float* __restrict__ Out) {
    constexpr int LDA = 40;    // halves: 80B row pitch -> conflict-free ldmatrix
    constexpr int LDB = 136;   // halves: 272B row pitch -> conflict-free ldmatrix.trans
    __shared__ __align__(16) __half As[128 * LDA];
    __shared__ __align__(16) __half Bs[32 * LDB];

    const int e   = blockIdx.z;
    const int cnt = g_counts[e];
    const int r0  = blockIdx.y * 128;
    if (r0 >= cnt) return;
    const int off = g_offs[e];
    const int n0  = blockIdx.x * 128;

    const int tid  = threadIdx.x;
    const int lane = tid & 31;
    const int gq   = lane >> 2;
    const int tg   = lane & 3;
    const int w    = tid >> 5;
    const int wm   = w & 1;        // 2 warps along M (64 each)
    const int wn   = w >> 1;       // 4 warps along N (32 each)

    // -- A global load mapping: 4 rows/thread, 4 k-elements per row per chunk
    const int arow = tid >> 3;     // 0..31
    const int ak4  = tid & 7;      // 0..7 (4-elem group within BK=32)
    const float*  aptrf[4];
    const __half* aptrh[4];
    bool aval[4];
#pragma unroll
    for (int j = 0; j < 4; j++) {
        int p = r0 + arow + 32 * j;
        bool v = p < cnt;
        aval[j] = v;
        if (MODE == 1) {
            int src = v ? g_perm[off + p] : 0;
            aptrf[j] = Asrc + (size_t)src * KDIM;
        } else {
            int src = v ? (off + p) : 0;
            aptrh[j] = g_hh + (size_t)src * KDIM;
        }
    }

    // -- B global load mapping: 2 k-rows/thread, one uint4 (8 halves) each
    const int br = tid >> 4;       // 0..15 (and +16)
    const int bc = tid & 15;       // 16B chunk within 128-half row
    const __half* whbase = (MODE == 1 ? g_w1h : g_w2h)   // device-side symbol
                           + (size_t)e * DIM * FF + n0;

    float acc[4][4][4];
#pragma unroll
    for (int i = 0; i < 4; i++)
#pragma unroll
        for (int jn = 0; jn < 4; jn++)
#pragma unroll
            for (int r = 0; r < 4; r++) acc[i][jn][r] = 0.f;

    // register staging for 2-stage software pipeline
    float4 rAf[4];
    float2 rAh[4];
    uint4  rBu[2];

    auto load_stage = [&](int kb) {
#pragma unroll
        for (int j = 0; j < 4; j++) {
            if (MODE == 1) {
                rAf[j] = aval[j] ? ((const float4*)(aptrf[j] + kb))[ak4]
                                 : make_float4(0.f, 0.f, 0.f, 0.f);
            } else {
                rAh[j] = aval[j] ? ((const float2*)(aptrh[j] + kb))[ak4]
                                 : make_float2(0.f, 0.f);
            }
        }
        const __half* bg = whbase + (size_t)(kb + br) * NDIM + bc * 8;
        rBu[0] = *(const uint4*)bg;
        rBu[1] = *(const uint4*)(bg + (size_t)16 * NDIM);
    };

    auto store_stage = [&]() {
#pragma unroll
        for (int j = 0; j < 4; j++) {
            __half* dst = As + (arow + 32 * j) * LDA + ak4 * 4;
            uint2 u;
            if (MODE == 1) {
                u.x = pack_h2(rAf[j].x, rAf[j].y);
                u.y = pack_h2(rAf[j].z, rAf[j].w);
            } else {
                u = *reinterpret_cast<uint2*>(&rAh[j]);   // raw 4 halves
            }
            *reinterpret_cast<uint2*>(dst) = u;
        }
        *reinterpret_cast<uint4*>(Bs + br * LDB + bc * 8)        = rBu[0];
        *reinterpret_cast<uint4*>(Bs + (br + 16) * LDB + bc * 8) = rBu[1];
    };

    load_stage(0);

    for (int kb = 0; kb < KDIM; kb += 32) {
        store_stage();
        __syncthreads();
        if (kb + 32 < KDIM) load_stage(kb + 32);   // overlap next LDG with math

#pragma unroll
        for (int kk = 0; kk < 2; kk++) {           // two k16 steps
            uint32_t af[4][4];
#pragma unroll
            for (int mt = 0; mt < 4; mt++) {
                const __half* p = As + (wm * 64 + mt * 16 + (lane & 15)) * LDA
                                     + kk * 16 + (lane >> 4) * 8;
                ldmat4(af[mt], p);
            }
            uint32_t bf[4][2];
#pragma unroll
            for (int nn = 0; nn < 2; nn++) {
                const __half* p = Bs + (kk * 16 + (lane & 15)) * LDB
                                     + wn * 32 + nn * 16 + (lane >> 4) * 8;
                uint32_t r[4];
                ldmat4t(r, p);
                bf[nn * 2 + 0][0] = r[0]; bf[nn * 2 + 0][1] = r[1];
                bf[nn * 2 + 1][0] = r[2]; bf[nn * 2 + 1][1] = r[3];
            }
#pragma unroll
            for (int mt = 0; mt < 4; mt++)
#pragma unroll
                for (int nt = 0; nt < 4; nt++)
                    mma16(acc[mt][nt], af[mt], bf[nt]);
        }
        __syncthreads();
    }

    // -- epilogue (c frag: c0,c1 = row g cols 2tg,2tg+1; c2,c3 = row g+8)
#pragma unroll
    for (int mt = 0; mt < 4; mt++) {
#pragma unroll
        for (int rr = 0; rr < 2; rr++) {
            int p = r0 + wm * 64 + mt * 16 + gq + rr * 8;
            if (p >= cnt) continue;
            if (MODE == 1) {
                __half* hrow = g_hh + (size_t)(off + p) * FF + n0 + wn * 32;
#pragma unroll
                for (int nt = 0; nt < 4; nt++) {
                    uint32_t v = pack_h2(fmaxf(acc[mt][nt][rr * 2 + 0], 0.f),
                                         fmaxf(acc[mt][nt][rr * 2 + 1], 0.f));
                    *reinterpret_cast<uint32_t*>(hrow + nt * 8 + tg * 2) = v;
                }
            } else {
                int t = g_perm[off + p];
                float gate = g_gate[t];
                float* orow = Out + (size_t)t * DIM + n0 + wn * 32;
#pragma unroll
                for (int nt = 0; nt < 4; nt++) {
                    float2 v;
                    v.x = acc[mt][nt][rr * 2 + 0] * gate;
                    v.y = acc[mt][nt][rr * 2 + 1] * gate;
                    *((float2*)(orow + nt * 8 + tg * 2)) = v;
                }
            }
        }
    }
}

// ---------------- launch -----------------------------------------------------
extern "C" void kernel_launch(void* const* d_in, const int* in_sizes, int n_in,
                              void* d_out, int out_size) {
    const float* x  = (const float*)d_in[0];
    const float* w1 = (const float*)d_in[1];
    const float* w2 = (const float*)d_in[2];
    const float* rw = (const float*)d_in[3];
    const float* rb = (const float*)d_in[4];
    float* out = (float*)d_out;

    const size_t wn4 = (size_t)NE * DIM * FF / 4;
    const int convgrid = (int)((wn4 + 255) / 256);

    init_kernel<<<1, 32>>>();
    router_kernel<<<T_TOK / 8, 256>>>(x, rw, rb);
    offs_loss_kernel<<<1, 32>>>(out + (size_t)out_size - 1);  // loss is last element
    scatter_kernel<<<T_TOK / 256, 256>>>();
    conv_kernel<1><<<convgrid, 256>>>(w1);
    conv_kernel<2><<<convgrid, 256>>>(w2);
    moe_gemm<1, DIM, FF><<<dim3(FF / 128, T_TOK / 128, NE), 256>>>(x,  nullptr);
    moe_gemm<2, FF, DIM><<<dim3(DIM / 128, T_TOK / 128, NE), 256>>>(nullptr, out);
}